// round 12
// baseline (speedup 1.0000x reference)
#include <cuda_runtime.h>
#include <math.h>

// ---------------------------------------------------------------------------
// 2-layer LSTM, B=16, S=2048, I=256, H=512, fp32.
// Persistent kernel, 128 CTAs (1/SM), weights pinned in SMEM.
// R11: 8x8 register tile, split-K=64, LDS.128 quad loads with 16B-interleaved
// k-groups (conflict-free), shuffle-reduce 64->8 slabs, sequential GEMMs
// reusing one 128-reg accumulator, MUFU cell activations.
// ---------------------------------------------------------------------------

#define BATCH 16
#define SEQ   2048
#define IDIM  256
#define HDIM  512
#define NCTA  128
#define NTHREADS 256
#define ROWS  16          // 4 units x 4 gates per CTA, per layer
#define UNITS 4
#define K0    768
#define K1    1024
#define P0    772         // pitches: % 4 == 0 (LDS.128), % 32 == 4 (banks)
#define P1    1028
#define PA    1284        // combined A pitch [x | h0 | h1]
#define KQ0   3           // k-quads per thread, GEMM0 (768/4/64)
#define KQ1   4           // k-quads per thread, GEMM1 (1024/4/64)
#define NSLAB 8           // slabs after 3-level shuffle reduce (64 kg -> 8)
#define SLAB  264         // padded slab pitch

// ---- global scratch ----
__device__ __align__(16) float g_h0[2][BATCH * HDIM];
__device__ __align__(16) float g_h1[2][BATCH * HDIM];
__device__ unsigned int g_f0[NCTA];     // f0 = fbase+j+1 <=> h0(j) published
__device__ unsigned int g_f1[NCTA];     // f1 = fbase+j+1 <=> h1(j) published
__device__ unsigned int g_bar_count = 0;
__device__ volatile unsigned int g_bar_epoch = 0;

// ---- acquire/release ----
__device__ __forceinline__ unsigned int ld_acq(const unsigned int* p) {
    unsigned int v;
    asm volatile("ld.acquire.gpu.u32 %0, [%1];" : "=r"(v) : "l"(p) : "memory");
    return v;
}
__device__ __forceinline__ void st_rel(unsigned int* p, unsigned int v) {
    asm volatile("st.release.gpu.u32 [%0], %1;" :: "l"(p), "r"(v) : "memory");
}

__device__ __forceinline__ void entry_barrier() {
    unsigned int ebase = 0;
    if (threadIdx.x == 0) ebase = g_bar_epoch;
    __syncthreads();
    if (threadIdx.x == 0) {
        __threadfence();
        unsigned int a = atomicAdd(&g_bar_count, 1u);
        unsigned int target = ebase + 1;
        if (a == NCTA - 1) {
            atomicExch(&g_bar_count, 0u);
            __threadfence();
            g_bar_epoch = target;
        } else {
            while ((int)(g_bar_epoch - target) < 0) { }
        }
        __threadfence();
    }
    __syncthreads();
}

__device__ __forceinline__ void wait_flags(unsigned int* f, unsigned int target) {
    if (threadIdx.x < NCTA) {
        while ((int)(ld_acq(&f[threadIdx.x]) - target) < 0) { }
    }
    __syncthreads();
}

// ---- packed f32x2 FMA ----
__device__ __forceinline__ void ffma2(unsigned long long& acc,
                                      unsigned long long a,
                                      unsigned long long b) {
    asm("fma.rn.f32x2 %0, %1, %2, %0;" : "+l"(acc) : "l"(a), "l"(b));
}
__device__ __forceinline__ float u2sum(unsigned long long v) {
    float lo, hi;
    asm("mov.b64 {%0,%1}, %2;" : "=f"(lo), "=f"(hi) : "l"(v));
    return lo + hi;
}

// ---- fast activations (MUFU; err ~1e-6, far under 1e-3 budget) ----
__device__ __forceinline__ float fsig(float x) {
    float e, r;
    asm("ex2.approx.f32 %0, %1;" : "=f"(e) : "f"(-1.4426950408889634f * x));
    asm("rcp.approx.f32 %0, %1;" : "=f"(r) : "f"(1.0f + e));
    return r;
}
__device__ __forceinline__ float ftanh(float x) {   // 2*sigmoid(2x) - 1
    float e, r;
    asm("ex2.approx.f32 %0, %1;" : "=f"(e) : "f"(-2.8853900817779268f * x));
    asm("rcp.approx.f32 %0, %1;" : "=f"(r) : "f"(1.0f + e));
    return 2.0f * r - 1.0f;
}

// ---- GEMM: C[16 x 16] via 8x8 register tile, split-K 64, LDS.128 ----
// tid: kg = tid>>2 (0..63), tr = (tid>>1)&1, tc = tid&1.
// k-quad index = q*64 + kg (16B interleave): float offset 4*(q*64+kg).
// Per quad: 16 LDS.128 -> 128 FFMA2.
template <int NQ, int WP, int AP>
__device__ __forceinline__ void gemm8x8(const float* __restrict__ sW,
                                        const float* __restrict__ sA,
                                        unsigned long long acc[8][8]) {
    const int tid = threadIdx.x;
    const int kg  = tid >> 2;
    const int tr  = (tid >> 1) & 1;
    const int tc  = tid & 1;

    const float* wb = sW + (8 * tr) * WP + 4 * kg;
    const float* ab = sA + (8 * tc) * AP + 4 * kg;

#pragma unroll 1
    for (int q = 0; q < NQ; ++q) {
        ulonglong2 wv[8], av[8];
#pragma unroll
        for (int i = 0; i < 8; ++i)
            wv[i] = *(const ulonglong2*)(wb + i * WP + q * 256);
#pragma unroll
        for (int j = 0; j < 8; ++j)
            av[j] = *(const ulonglong2*)(ab + j * AP + q * 256);
#pragma unroll
        for (int i = 0; i < 8; ++i)
#pragma unroll
            for (int j = 0; j < 8; ++j) {
                ffma2(acc[i][j], wv[i].x, av[j].x);
                ffma2(acc[i][j], wv[i].y, av[j].y);
            }
    }
}

// shuffle-reduce 8 kg per warp (lane bits 2,3,4), store 8 slabs
__device__ __forceinline__ void store_acc8(unsigned long long acc[8][8],
                                           float* __restrict__ sGp) {
    const int tid  = threadIdx.x;
    const int lane = tid & 31;
    const int warp = tid >> 5;
    const int tr   = (tid >> 1) & 1;
    const int tc   = tid & 1;
    float* dst = sGp + warp * SLAB;
    const bool w0 = (lane & 28) == 0;
#pragma unroll
    for (int i = 0; i < 8; ++i)
#pragma unroll
        for (int j = 0; j < 8; ++j) {
            float v = u2sum(acc[i][j]);
            v += __shfl_xor_sync(0xffffffffu, v, 4);
            v += __shfl_xor_sync(0xffffffffu, v, 8);
            v += __shfl_xor_sync(0xffffffffu, v, 16);
            if (w0) dst[(8 * tr + i) * 16 + 8 * tc + j] = v;
        }
}

__global__ void __launch_bounds__(NTHREADS, 1)
lstm2_persistent(const float* __restrict__ x,
                 const float* __restrict__ W0,
                 const float* __restrict__ b0,
                 const float* __restrict__ W1,
                 const float* __restrict__ b1,
                 float* __restrict__ out) {
    extern __shared__ float smem[];
    float* sW0 = smem;                      // 16*772
    float* sW1 = sW0 + ROWS * P0;           // 16*1028
    float* sAB = sW1 + ROWS * P1;           // 16*1284  [x | h0 | h1]
    float* sGp = sAB + BATCH * PA;          // 8*264 (shared by both layers)
    float* sB0 = sGp + NSLAB * SLAB;        // 16
    float* sB1 = sB0 + 16;                  // 16

    const int m   = blockIdx.x;
    const int tid = threadIdx.x;
    const int u0  = m * UNITS;

    // ---- persistent weight slices (row r = u*4 + gate), float4 loads ----
    for (int idx = tid; idx < ROWS * (K0 / 4); idx += NTHREADS) {
        int r = idx / (K0 / 4), k4 = idx % (K0 / 4);
        int gg = r & 3, u = r >> 2;
        int grow = gg * HDIM + u0 + u;
        ((float4*)(sW0 + r * P0))[k4] =
            ((const float4*)(W0 + (size_t)grow * K0))[k4];
    }
    for (int idx = tid; idx < ROWS * (K1 / 4); idx += NTHREADS) {
        int r = idx / (K1 / 4), k4 = idx % (K1 / 4);
        int gg = r & 3, u = r >> 2;
        int grow = gg * HDIM + u0 + u;
        ((float4*)(sW1 + r * P1))[k4] =
            ((const float4*)(W1 + (size_t)grow * K1))[k4];
    }
    if (tid < ROWS) {
        int gg = tid & 3, u = tid >> 2;
        sB0[tid] = b0[gg * HDIM + u0 + u];
        sB1[tid] = b1[gg * HDIM + u0 + u];
    }

    const int uu = tid >> 4;                // cell role (tid < 64)
    const int bb = tid & 15;
    float c0 = 0.f, c1 = 0.f, h0r = 0.f, h1r = 0.f;

    const unsigned int fbase = g_f0[m];     // replay-safe

    if (tid < 64) {
        g_h0[1][bb * HDIM + u0 + uu] = 0.f; // h0(-1)
        g_h1[1][bb * HDIM + u0 + uu] = 0.f; // h1(-1)
    }
    entry_barrier();

    unsigned long long acc[8][8];

    // Iteration i: computes h0(i) (i<SEQ) and h1(i-1) (i>0).
    for (int i = 0; i <= SEQ; ++i) {
        const unsigned int seq = fbase + (unsigned)i;

        // ---- stage x(i) (float4) ----
        if (i < SEQ) {
            const float* xrow = x + (size_t)i * IDIM;
            for (int idx = tid; idx < BATCH * (IDIM / 4); idx += NTHREADS) {
                int b = idx >> 6, k4 = idx & 63;
                *(float4*)(sAB + b * PA + 4 * k4) =
                    *(const float4*)(xrow + (size_t)b * SEQ * IDIM + 4 * k4);
            }
        }

        // ---- stage h1(i-2) (cold wait) ----
        wait_flags(g_f1, seq - 1u);
        {
            const float* src = g_h1[i & 1];
            for (int idx = tid; idx < BATCH * (HDIM / 4); idx += NTHREADS) {
                int b = idx >> 7, k4 = idx & 127;
                float4 v = __ldcg((const float4*)(src + b * HDIM + 4 * k4));
                *(float4*)(sAB + b * PA + IDIM + HDIM + 4 * k4) = v;
            }
        }

        // ---- stage h0(i-1) (hot wait) ----
        wait_flags(g_f0, seq);
        {
            const float* src = g_h0[(i + 1) & 1];
            for (int idx = tid; idx < BATCH * (HDIM / 4); idx += NTHREADS) {
                int b = idx >> 7, k4 = idx & 127;
                float4 v = __ldcg((const float4*)(src + b * HDIM + 4 * k4));
                *(float4*)(sAB + b * PA + IDIM + 4 * k4) = v;
            }
        }
        __syncthreads();                    // S0: sAB complete

        // ---- GEMM0: W0 @ [x ; h0] ----
        if (i < SEQ) {
#pragma unroll
            for (int a = 0; a < 8; ++a)
#pragma unroll
                for (int b = 0; b < 8; ++b) acc[a][b] = 0ull;
            gemm8x8<KQ0, P0, PA>(sW0, sAB, acc);
            store_acc8(acc, sGp);
        }
        __syncthreads();                    // S1: sGp0 complete

        // ---- cell0 + publish h0(i) FIRST (critical), others start GEMM1 ----
        if (i < SEQ && tid < 64) {
            float g4[4];
#pragma unroll
            for (int gg = 0; gg < 4; ++gg) {
                float r = sB0[uu * 4 + gg];
                const int o = (uu * 4 + gg) * 16 + bb;
#pragma unroll
                for (int s = 0; s < NSLAB; ++s) r += sGp[s * SLAB + o];
                g4[gg] = r;
            }
            float ig = fsig(g4[0]);
            float fg = fsig(g4[1]);
            float cg = ftanh(g4[2]);
            float og = fsig(g4[3]);
            c0  = fg * c0 + ig * cg;
            h0r = og * ftanh(c0);
            g_h0[i & 1][bb * HDIM + u0 + uu] = h0r;
            asm volatile("bar.sync 1, 64;" ::: "memory");
            if (tid == 0) st_rel(&g_f0[m], seq + 1u);   // h0(i) live
        }

        // ---- GEMM1: W1 @ [h0 ; h1] (all threads) ----
        if (i > 0) {
#pragma unroll
            for (int a = 0; a < 8; ++a)
#pragma unroll
                for (int b = 0; b < 8; ++b) acc[a][b] = 0ull;
            gemm8x8<KQ1, P1, PA>(sW1, sAB + IDIM, acc);
        }
        __syncthreads();                    // S2: cell0 slab reads done
        if (i > 0) store_acc8(acc, sGp);
        __syncthreads();                    // S3: sGp1 complete

        // ---- cell1 + publish h1(i-1) (lazy) ----
        if (i > 0 && tid < 64) {
            float g4[4];
#pragma unroll
            for (int gg = 0; gg < 4; ++gg) {
                float r = sB1[uu * 4 + gg];
                const int o = (uu * 4 + gg) * 16 + bb;
#pragma unroll
                for (int s = 0; s < NSLAB; ++s) r += sGp[s * SLAB + o];
                g4[gg] = r;
            }
            float ig = fsig(g4[0]);
            float fg = fsig(g4[1]);
            float cg = ftanh(g4[2]);
            float og = fsig(g4[3]);
            c1  = fg * c1 + ig * cg;
            h1r = og * ftanh(c1);
            g_h1[(i - 1) & 1][bb * HDIM + u0 + uu] = h1r;
            out[((size_t)bb * SEQ + (i - 1)) * HDIM + u0 + uu] = h1r;
            asm volatile("bar.sync 2, 64;" ::: "memory");
            if (tid == 0) st_rel(&g_f1[m], seq);        // h1(i-1) live
        }
        // cell1's slab reads finish before this thread-group reaches the
        // next iteration's wait_flags __syncthreads; the next slab write
        // (store_acc8 for GEMM0) is after S1 — ordered. sAB restaging is
        // safe: all gemm reads ended before S2.
    }

    // ---- final (h, c): [2,B,H] h then [2,B,H] c, after outputs[B,S,H] ----
    if (tid < 64) {
        const size_t OH = (size_t)BATCH * SEQ * HDIM;
        const size_t BH = (size_t)BATCH * HDIM;
        const size_t o  = (size_t)bb * HDIM + u0 + uu;
        out[OH + 0 * BH + o] = h0r;
        out[OH + 1 * BH + o] = h1r;
        out[OH + 2 * BH + o] = c0;
        out[OH + 3 * BH + o] = c1;
    }
}

extern "C" void kernel_launch(void* const* d_in, const int* in_sizes, int n_in,
                              void* d_out, int out_size) {
    const float* x  = (const float*)d_in[0];
    const float* W0 = (const float*)d_in[1];
    const float* b0 = (const float*)d_in[2];
    const float* W1 = (const float*)d_in[3];
    const float* b1 = (const float*)d_in[4];
    float* out = (float*)d_out;

    const int smem_floats = ROWS * P0 + ROWS * P1 + BATCH * PA +
                            NSLAB * SLAB + 64;
    const int smem_bytes = smem_floats * (int)sizeof(float);   // ~206 KB

    cudaFuncSetAttribute(lstm2_persistent,
                         cudaFuncAttributeMaxDynamicSharedMemorySize,
                         smem_bytes);

    lstm2_persistent<<<NCTA, NTHREADS, smem_bytes>>>(x, W0, b0, W1, b1, out);
}

// round 13
// speedup vs baseline: 1.4282x; 1.4282x over previous
#include <cuda_runtime.h>
#include <math.h>

// ---------------------------------------------------------------------------
// 2-layer LSTM, B=16, S=2048, I=256, H=512, fp32.
// Persistent kernel, 128 CTAs (1/SM), weights pinned in SMEM (k-major).
// R12: packed row-pair GEMM.
//   W transposed once to [k][16] layout -> LDS.64 yields 2 gate rows/k.
//   A scalar LDS.32 + mov.b64{a,a} duplicate -> FFMA2 computes 2 rows at once.
//   acc[4 row-pairs][8 cols] = 64 regs (no spill), SMEM bytes halved vs 4x4.
//   Split-K 64, 3-level xor-shuffle reduce -> 8 slabs, col-major slabs so the
//   cell reduce is 8 conflict-free LDS.128.
//   Flags/pipelining from R10, MUFU activations from R11.
// ---------------------------------------------------------------------------

#define BATCH 16
#define SEQ   2048
#define IDIM  256
#define HDIM  512
#define NCTA  128
#define NTHREADS 256
#define ROWS  16          // 4 units x 4 gates per CTA, per layer
#define UNITS 4
#define K0    768
#define K1    1024
#define WP    18          // k-major weight pitch (floats): 16 rows + 2 pad
#define PA    1286        // A pitch [x | h0 | h1]: 8*PA % 32 == 16
#define SP    20          // slab pitch (col-major), %4==0 for LDS.128
#define SLABSZ (16*SP)    // 320 floats per warp slab
#define NQ0   12          // 768/64
#define NQ1   16          // 1024/64

typedef unsigned long long ull;

// ---- global scratch ----
__device__ __align__(16) float g_h0[2][BATCH * HDIM];
__device__ __align__(16) float g_h1[2][BATCH * HDIM];
__device__ unsigned int g_f0[NCTA];
__device__ unsigned int g_f1[NCTA];
__device__ unsigned int g_bar_count = 0;
__device__ volatile unsigned int g_bar_epoch = 0;

__device__ __forceinline__ unsigned int ld_acq(const unsigned int* p) {
    unsigned int v;
    asm volatile("ld.acquire.gpu.u32 %0, [%1];" : "=r"(v) : "l"(p) : "memory");
    return v;
}
__device__ __forceinline__ void st_rel(unsigned int* p, unsigned int v) {
    asm volatile("st.release.gpu.u32 [%0], %1;" :: "l"(p), "r"(v) : "memory");
}

__device__ __forceinline__ void entry_barrier() {
    unsigned int ebase = 0;
    if (threadIdx.x == 0) ebase = g_bar_epoch;
    __syncthreads();
    if (threadIdx.x == 0) {
        __threadfence();
        unsigned int a = atomicAdd(&g_bar_count, 1u);
        unsigned int target = ebase + 1;
        if (a == NCTA - 1) {
            atomicExch(&g_bar_count, 0u);
            __threadfence();
            g_bar_epoch = target;
        } else {
            while ((int)(g_bar_epoch - target) < 0) { }
        }
        __threadfence();
    }
    __syncthreads();
}

__device__ __forceinline__ void wait_flags(unsigned int* f, unsigned int target) {
    if (threadIdx.x < NCTA) {
        while ((int)(ld_acq(&f[threadIdx.x]) - target) < 0) { }
    }
    __syncthreads();
}

// ---- packed f32x2 helpers ----
__device__ __forceinline__ void ffma2(ull& acc, ull a, ull b) {
    asm("fma.rn.f32x2 %0, %1, %2, %0;" : "+l"(acc) : "l"(a), "l"(b));
}
__device__ __forceinline__ ull dup2(float a) {
    ull r;
    asm("mov.b64 %0, {%1, %1};" : "=l"(r) : "f"(a));
    return r;
}
__device__ __forceinline__ void unpack2(ull v, float& lo, float& hi) {
    asm("mov.b64 {%0, %1}, %2;" : "=f"(lo), "=f"(hi) : "l"(v));
}

// ---- fast activations (MUFU; validated rel_err ~2e-6 in R11) ----
__device__ __forceinline__ float fsig(float x) {
    float e, r;
    asm("ex2.approx.f32 %0, %1;" : "=f"(e) : "f"(-1.4426950408889634f * x));
    asm("rcp.approx.f32 %0, %1;" : "=f"(r) : "f"(1.0f + e));
    return r;
}
__device__ __forceinline__ float ftanh(float x) {
    float e, r;
    asm("ex2.approx.f32 %0, %1;" : "=f"(e) : "f"(-2.8853900817779268f * x));
    asm("rcp.approx.f32 %0, %1;" : "=f"(r) : "f"(1.0f + e));
    return 2.0f * r - 1.0f;
}

// ---- packed GEMM: C[16 rows x 16 cols], acc = [4 row-pairs][8 cols] ----
// tid: kg = tid>>2 (0..63), tr = (tid>>1)&1 (row half), tc = tid&1 (col half).
// k = q*64 + kg. Per k: 4 LDS.64 (w row-pairs) + 8 LDS.32 (a) + 8 dup + 32 FFMA2.
template <int NQ>
__device__ __forceinline__ void gemm_packed(const float* __restrict__ sWt,
                                            const float* __restrict__ sA,
                                            ull acc[4][8]) {
    const int tid = threadIdx.x;
    const int kg  = tid >> 2;
    const int tr  = (tid >> 1) & 1;
    const int tc  = tid & 1;

    const float* wb = sWt + kg * WP + 8 * tr;       // + 2*rp for row-pair rp
    const float* ab = sA + (8 * tc) * PA + kg;      // + j*PA for col j

#pragma unroll 1
    for (int q = 0; q < NQ; ++q) {
        const float* w = wb + q * (64 * WP);
        const float* a = ab + q * 64;

        float av[8];
#pragma unroll
        for (int j = 0; j < 8; ++j) av[j] = a[j * PA];
        ull ad[8];
#pragma unroll
        for (int j = 0; j < 8; ++j) ad[j] = dup2(av[j]);

        ull wv[4];
#pragma unroll
        for (int rp = 0; rp < 4; ++rp) wv[rp] = *(const ull*)(w + 2 * rp);

#pragma unroll
        for (int rp = 0; rp < 4; ++rp)
#pragma unroll
            for (int j = 0; j < 8; ++j)
                ffma2(acc[rp][j], wv[rp], ad[j]);
    }
}

// 3-level xor-shuffle reduce over the 8 kg per warp, store to this warp's slab
// (col-major: slab[col*SP + row], rows = 8tr+2rp+{0,1}).
__device__ __forceinline__ void reduce_store(ull acc[4][8],
                                             float* __restrict__ slab) {
    const int tid  = threadIdx.x;
    const int lane = tid & 31;
    const int tr   = (tid >> 1) & 1;
    const int tc   = tid & 1;
    const bool st  = (lane & 28) == 0;   // lanes 0..3 hold (tr,tc) positions
#pragma unroll
    for (int rp = 0; rp < 4; ++rp)
#pragma unroll
        for (int j = 0; j < 8; ++j) {
            float lo, hi;
            unpack2(acc[rp][j], lo, hi);
            lo += __shfl_xor_sync(0xffffffffu, lo, 4);
            hi += __shfl_xor_sync(0xffffffffu, hi, 4);
            lo += __shfl_xor_sync(0xffffffffu, lo, 8);
            hi += __shfl_xor_sync(0xffffffffu, hi, 8);
            lo += __shfl_xor_sync(0xffffffffu, lo, 16);
            hi += __shfl_xor_sync(0xffffffffu, hi, 16);
            if (st) {
                float* d = slab + (8 * tc + j) * SP + 8 * tr + 2 * rp;
                d[0] = lo;
                d[1] = hi;
            }
        }
}

__global__ void __launch_bounds__(NTHREADS, 1)
lstm2_persistent(const float* __restrict__ x,
                 const float* __restrict__ W0,
                 const float* __restrict__ b0,
                 const float* __restrict__ W1,
                 const float* __restrict__ b1,
                 float* __restrict__ out) {
    extern __shared__ float smem[];
    float* sW0t = smem;                     // 768*18  = 13824
    float* sW1t = sW0t + K0 * WP;           // 1024*18 = 18432
    float* sA   = sW1t + K1 * WP;           // 16*1286 = 20576  [x | h0 | h1]
    float* sSl  = sA + BATCH * PA;          // 8*320   = 2560   warp slabs
    float* sB0  = sSl + 8 * SLABSZ;         // 16
    float* sB1  = sB0 + 16;                 // 16

    const int m   = blockIdx.x;
    const int tid = threadIdx.x;
    const int u0  = m * UNITS;

    // ---- one-time: transpose weight slices into k-major SMEM ----
    // slice row r = u*4 + gate  <->  global row gate*HDIM + u0 + u
    for (int idx = tid; idx < ROWS * K0; idx += NTHREADS) {
        int r = idx / K0, k = idx % K0;
        int gg = r & 3, u = r >> 2;
        sW0t[k * WP + r] = W0[(size_t)(gg * HDIM + u0 + u) * K0 + k];
    }
    for (int idx = tid; idx < ROWS * K1; idx += NTHREADS) {
        int r = idx / K1, k = idx % K1;
        int gg = r & 3, u = r >> 2;
        sW1t[k * WP + r] = W1[(size_t)(gg * HDIM + u0 + u) * K1 + k];
    }
    if (tid < ROWS) {
        int gg = tid & 3, u = tid >> 2;
        sB0[tid] = b0[gg * HDIM + u0 + u];
        sB1[tid] = b1[gg * HDIM + u0 + u];
    }

    const int uu = tid >> 4;                // cell role (tid < 64)
    const int bb = tid & 15;
    float c0 = 0.f, c1 = 0.f, h0r = 0.f, h1r = 0.f;

    const unsigned int fbase = g_f0[m];     // replay-safe

    if (tid < 64) {
        g_h0[1][bb * HDIM + u0 + uu] = 0.f; // h0(-1)
        g_h1[1][bb * HDIM + u0 + uu] = 0.f; // h1(-1)
    }
    entry_barrier();

    ull acc[4][8];

    // Iteration i: computes h0(i) (i<SEQ) and h1(i-1) (i>0).
    for (int i = 0; i <= SEQ; ++i) {
        const unsigned int seq = fbase + (unsigned)i;

        // ---- stage x(i) (float2, pitch PA) ----
        if (i < SEQ) {
            const float* xrow = x + (size_t)i * IDIM;
            for (int idx = tid; idx < BATCH * (IDIM / 2); idx += NTHREADS) {
                int b = idx >> 7, k = (idx & 127) * 2;
                *(float2*)(sA + b * PA + k) =
                    *(const float2*)(xrow + (size_t)b * SEQ * IDIM + k);
            }
        }

        // ---- stage h1(i-2) (cold wait, 1 step slack) ----
        wait_flags(g_f1, seq - 1u);
        {
            const float* src = g_h1[i & 1];
            for (int idx = tid; idx < BATCH * (HDIM / 2); idx += NTHREADS) {
                int b = idx >> 8, k = (idx & 255) * 2;
                float2 v = __ldcg((const float2*)(src + b * HDIM + k));
                *(float2*)(sA + b * PA + IDIM + HDIM + k) = v;
            }
        }

        // ---- stage h0(i-1) (hot wait) ----
        wait_flags(g_f0, seq);
        {
            const float* src = g_h0[(i + 1) & 1];
            for (int idx = tid; idx < BATCH * (HDIM / 2); idx += NTHREADS) {
                int b = idx >> 8, k = (idx & 255) * 2;
                float2 v = __ldcg((const float2*)(src + b * HDIM + k));
                *(float2*)(sA + b * PA + IDIM + k) = v;
            }
        }
        __syncthreads();                    // S0: sA complete

        // ---- GEMM0: W0 @ [x ; h0(i-1)] ----
        if (i < SEQ) {
#pragma unroll
            for (int a = 0; a < 4; ++a)
#pragma unroll
                for (int b = 0; b < 8; ++b) acc[a][b] = 0ull;
            gemm_packed<NQ0>(sW0t, sA, acc);
            reduce_store(acc, sSl + (tid >> 5) * SLABSZ);
        }
        __syncthreads();                    // S1: slabs(GEMM0) complete

        // ---- cell0 + publish h0(i) FIRST (critical path) ----
        if (i < SEQ && tid < 64) {
            const float* base = sSl + bb * SP + 4 * uu;
            float4 s = *(const float4*)(sB0 + 4 * uu);
#pragma unroll
            for (int w = 0; w < 8; ++w) {
                float4 v = *(const float4*)(base + w * SLABSZ);
                s.x += v.x; s.y += v.y; s.z += v.z; s.w += v.w;
            }
            float ig = fsig(s.x);
            float fg = fsig(s.y);
            float cg = ftanh(s.z);
            float og = fsig(s.w);
            c0  = fg * c0 + ig * cg;
            h0r = og * ftanh(c0);
            g_h0[i & 1][bb * HDIM + u0 + uu] = h0r;
            asm volatile("bar.sync 1, 64;" ::: "memory");
            if (tid == 0) st_rel(&g_f0[m], seq + 1u);   // h0(i) live
        }

        // ---- GEMM1: W1 @ [h0(i-1) ; h1(i-2)] = gates1(i-1) ----
        if (i > 0) {
#pragma unroll
            for (int a = 0; a < 4; ++a)
#pragma unroll
                for (int b = 0; b < 8; ++b) acc[a][b] = 0ull;
            gemm_packed<NQ1>(sW1t, sA + IDIM, acc);
        }
        __syncthreads();                    // S2: cell0 slab reads done
        if (i > 0) reduce_store(acc, sSl + (tid >> 5) * SLABSZ);
        __syncthreads();                    // S3: slabs(GEMM1) complete

        // ---- cell1 + publish h1(i-1) (lazy) ----
        if (i > 0 && tid < 64) {
            const float* base = sSl + bb * SP + 4 * uu;
            float4 s = *(const float4*)(sB1 + 4 * uu);
#pragma unroll
            for (int w = 0; w < 8; ++w) {
                float4 v = *(const float4*)(base + w * SLABSZ);
                s.x += v.x; s.y += v.y; s.z += v.z; s.w += v.w;
            }
            float ig = fsig(s.x);
            float fg = fsig(s.y);
            float cg = ftanh(s.z);
            float og = fsig(s.w);
            c1  = fg * c1 + ig * cg;
            h1r = og * ftanh(c1);
            g_h1[(i - 1) & 1][bb * HDIM + u0 + uu] = h1r;
            out[((size_t)bb * SEQ + (i - 1)) * HDIM + u0 + uu] = h1r;
            asm volatile("bar.sync 2, 64;" ::: "memory");
            if (tid == 0) st_rel(&g_f1[m], seq);        // h1(i-1) live
        }
        // Safety: next iter's slab write (reduce_store) happens only after all
        // threads (incl. cell1) pass the next S1; sA restaging races no reads
        // (gemm reads ended before S2; cells don't read sA).
    }

    // ---- final (h, c): [2,B,H] h then [2,B,H] c, after outputs[B,S,H] ----
    if (tid < 64) {
        const size_t OH = (size_t)BATCH * SEQ * HDIM;
        const size_t BH = (size_t)BATCH * HDIM;
        const size_t o  = (size_t)bb * HDIM + u0 + uu;
        out[OH + 0 * BH + o] = h0r;
        out[OH + 1 * BH + o] = h1r;
        out[OH + 2 * BH + o] = c0;
        out[OH + 3 * BH + o] = c1;
    }
}

extern "C" void kernel_launch(void* const* d_in, const int* in_sizes, int n_in,
                              void* d_out, int out_size) {
    const float* x  = (const float*)d_in[0];
    const float* W0 = (const float*)d_in[1];
    const float* b0 = (const float*)d_in[2];
    const float* W1 = (const float*)d_in[3];
    const float* b1 = (const float*)d_in[4];
    float* out = (float*)d_out;

    const int smem_floats = K0 * WP + K1 * WP + BATCH * PA +
                            8 * SLABSZ + 32;
    const int smem_bytes = smem_floats * (int)sizeof(float);  // 221,824 B

    cudaFuncSetAttribute(lstm2_persistent,
                         cudaFuncAttributeMaxDynamicSharedMemorySize,
                         smem_bytes);

    lstm2_persistent<<<NCTA, NTHREADS, smem_bytes>>>(x, W0, b0, W1, b1, out);
}